// round 14
// baseline (speedup 1.0000x reference)
#include <cuda_runtime.h>
#include <cuda_bf16.h>

#define NT 512
typedef unsigned long long u64;
typedef unsigned int u32;
typedef unsigned short u16;

static constexpr int L = 64, D = 128, H = 8;

// ---- byte offsets (all regions stride 272B for bf16 [64/128 rows][128 cols]) ----
static constexpr int B_AQHI = 0;       // xq hi -> Qa hi -> TV hi -> proj f32 (br0)
static constexpr int B_AQLO = 17408;   // xq lo -> Qa lo -> TV lo
static constexpr int B_AKHI = 34816;   // xk hi -> Kb hi -> CT hi -> proj f32 (br1)
static constexpr int B_AKLO = 52224;   // xk lo -> Kb lo -> CT lo
static constexpr int B_WHI  = 69632;   // W hi   | Vb hi/lo   | W-epi hi
static constexpr int B_WLO  = 104448;  // W lo   | XTb hi/lo  | W-epi lo
static constexpr int B_VBHI = 69632;
static constexpr int B_VBLO = 87040;
static constexpr int B_XTHI = 104448;
static constexpr int B_XTLO = 121856;
static constexpr int SM_BYTES = 139392;

// ---------------- helpers ----------------
static __device__ __forceinline__ void ldsm4(u32* r, u32 addr) {
    asm volatile("ldmatrix.sync.aligned.m8n8.x4.shared.b16 {%0,%1,%2,%3}, [%4];"
        : "=r"(r[0]), "=r"(r[1]), "=r"(r[2]), "=r"(r[3]) : "r"(addr));
}
static __device__ __forceinline__ void ldsm4t(u32* r, u32 addr) {
    asm volatile("ldmatrix.sync.aligned.m8n8.x4.trans.shared.b16 {%0,%1,%2,%3}, [%4];"
        : "=r"(r[0]), "=r"(r[1]), "=r"(r[2]), "=r"(r[3]) : "r"(addr));
}
static __device__ __forceinline__ void mmabf(float* d, const u32* a, u32 b0, u32 b1) {
    asm volatile("mma.sync.aligned.m16n8k16.row.col.f32.bf16.bf16.f32 "
        "{%0,%1,%2,%3}, {%4,%5,%6,%7}, {%8,%9}, {%0,%1,%2,%3};"
        : "+f"(d[0]), "+f"(d[1]), "+f"(d[2]), "+f"(d[3])
        : "r"(a[0]), "r"(a[1]), "r"(a[2]), "r"(a[3]), "r"(b0), "r"(b1));
}
static __device__ __forceinline__ void split2(float a, float b, u32& hi, u32& lo) {
    __nv_bfloat162 h2 = __floats2bfloat162_rn(a, b);
    __nv_bfloat162 l2 = __floats2bfloat162_rn(a - __bfloat162float(h2.x),
                                              b - __bfloat162float(h2.y));
    hi = *reinterpret_cast<u32*>(&h2);
    lo = *reinterpret_cast<u32*>(&l2);
}
static __device__ __forceinline__ void bsplit4(float4 v, u64& hi, u64& lo) {
    u16 h[4], l[4];
    float x[4] = {v.x, v.y, v.z, v.w};
#pragma unroll
    for (int i = 0; i < 4; i++) {
        __nv_bfloat16 bh = __float2bfloat16(x[i]);
        h[i] = __bfloat16_as_ushort(bh);
        l[i] = __bfloat16_as_ushort(__float2bfloat16(x[i] - __bfloat162float(bh)));
    }
    hi = (u64)h[0] | ((u64)h[1] << 16) | ((u64)h[2] << 32) | ((u64)h[3] << 48);
    lo = (u64)l[0] | ((u64)l[1] << 16) | ((u64)l[2] << 32) | ((u64)l[3] << 48);
}

// 3-pass bf16-split GEMM 64x128x128: warp tile 16m x 32n. A/W stride 272B.
static __device__ __forceinline__ void gemm3(u32 sb, u32 aHi, u32 aLo,
                                             int lane, int m0, int n0, float d[16]) {
    const u32 aoff = (u32)((m0 + (lane & 15)) * 272 + (lane >> 4) * 16);
    const u32 brow = (u32)(((lane & 7) + ((lane >> 4) << 3)) * 272 + ((lane >> 3) & 1) * 16);
    const u32 b0o = brow + (u32)(n0 * 272);
    const u32 b1o = b0o + 16 * 272;
#pragma unroll
    for (int kk = 0; kk < 8; ++kk) {
        const u32 ka = (u32)(kk * 32);
        u32 ah[4], al[4], bh0[4], bh1[4], bl0[4], bl1[4];
        ldsm4(ah, sb + aHi + aoff + ka);
        ldsm4(al, sb + aLo + aoff + ka);
        ldsm4(bh0, sb + B_WHI + b0o + ka);
        ldsm4(bh1, sb + B_WHI + b1o + ka);
        ldsm4(bl0, sb + B_WLO + b0o + ka);
        ldsm4(bl1, sb + B_WLO + b1o + ka);
#pragma unroll
        for (int t = 0; t < 4; ++t) {
            const u32* bh = (t < 2) ? bh0 : bh1;
            const u32* bl = (t < 2) ? bl0 : bl1;
            const int s = (t & 1) * 2;
            mmabf(d + 4 * t, ah, bh[s], bh[s + 1]);
            mmabf(d + 4 * t, ah, bl[s], bl[s + 1]);
            mmabf(d + 4 * t, al, bh[s], bh[s + 1]);
        }
    }
}

__global__ void __launch_bounds__(NT, 1)
fused_attn_kernel(const float* __restrict__ xq_g, const float* __restrict__ xk_g,
                  const float* __restrict__ xt_g,
                  const float* __restrict__ Wq,  const float* __restrict__ bq,
                  const float* __restrict__ Wk,  const float* __restrict__ bk,
                  const float* __restrict__ Wv,  const float* __restrict__ bv,
                  const float* __restrict__ Wot, const float* __restrict__ bot,
                  const float* __restrict__ Wtg, const float* __restrict__ btg,
                  const float* __restrict__ g_time, const float* __restrict__ b_time,
                  const float* __restrict__ g_tgt,  const float* __restrict__ b_tgt,
                  float* __restrict__ out, int BN)
{
    extern __shared__ float sm[];
    char* smc = reinterpret_cast<char*>(sm);
    const u32 sb = (u32)__cvta_generic_to_shared(sm);
    const int tid = threadIdx.x, bn = blockIdx.x;
    const int wid = tid >> 5, lane = tid & 31;
    const int m0 = 16 * (wid >> 2), n0 = 32 * (wid & 3);
    const int r1 = m0 + (lane >> 2), cb = 2 * (lane & 3);

    const float* xq_src = xq_g + (size_t)bn * (L * D);
    const float* xk_src = xk_g + (size_t)bn * (L * D);
    const float* xt_src = xt_g + (size_t)bn * (L * D);

    const size_t attnElems = (size_t)BN * H * (L * L);
    float* tv_base = out + attnElems + (size_t)bn * (L * D);
    float* ct_base = out + attnElems + (size_t)BN * (L * D) + (size_t)bn * (L * D);

    // W^T bf16 hi/lo stager: B[n][k] = W[k][n], stride 272B
    auto stageW = [&](const float* W) {
        for (int u = tid; u < 4096; u += NT) {
            int n = u & 127, k0 = 4 * (u >> 7);
            float4 v;
            v.x = __ldg(W + (k0 + 0) * D + n);
            v.y = __ldg(W + (k0 + 1) * D + n);
            v.z = __ldg(W + (k0 + 2) * D + n);
            v.w = __ldg(W + (k0 + 3) * D + n);
            u64 hi, lo; bsplit4(v, hi, lo);
            *reinterpret_cast<u64*>(smc + B_WHI + n * 272 + k0 * 2) = hi;
            *reinterpret_cast<u64*>(smc + B_WLO + n * 272 + k0 * 2) = lo;
        }
    };
    // split-pair store into a 272-stride bf16 region pair
    auto stsplit = [&](int baseHi, int baseLo, int r, int c, float a, float b) {
        u32 hi, lo; split2(a, b, hi, lo);
        *reinterpret_cast<u32*>(smc + baseHi + r * 272 + c * 2) = hi;
        *reinterpret_cast<u32*>(smc + baseLo + r * 272 + c * 2) = lo;
    };

    // ---- stage xq, xk bf16 hi/lo ----
    for (int u = tid; u < 2048; u += NT) {
        int m = u >> 5, k0 = 4 * (u & 31);
        u64 hi, lo;
        bsplit4(__ldg(reinterpret_cast<const float4*>(xq_src + m * D + k0)), hi, lo);
        *reinterpret_cast<u64*>(smc + B_AQHI + m * 272 + k0 * 2) = hi;
        *reinterpret_cast<u64*>(smc + B_AQLO + m * 272 + k0 * 2) = lo;
        bsplit4(__ldg(reinterpret_cast<const float4*>(xk_src + m * D + k0)), hi, lo);
        *reinterpret_cast<u64*>(smc + B_AKHI + m * 272 + k0 * 2) = hi;
        *reinterpret_cast<u64*>(smc + B_AKLO + m * 272 + k0 * 2) = lo;
    }
    stageW(Wq);
    __syncthreads();

    // ================= Q = xq @ Wq + bq -> Qa (A-layout, over AQ) =========
    {
        float d[16] = {0,0,0,0,0,0,0,0,0,0,0,0,0,0,0,0};
        gemm3(sb, B_AQHI, B_AQLO, lane, m0, n0, d);
        __syncthreads();
#pragma unroll
        for (int t = 0; t < 4; ++t) {
            int c = n0 + 8 * t + cb;
            float2 bb = __ldg(reinterpret_cast<const float2*>(bq + c));
            stsplit(B_AQHI, B_AQLO, r1,     c, d[4*t]   + bb.x, d[4*t+1] + bb.y);
            stsplit(B_AQHI, B_AQLO, r1 + 8, c, d[4*t+2] + bb.x, d[4*t+3] + bb.y);
        }
        stageW(Wk);
    }
    __syncthreads();

    // ================= K = xk @ Wk + bk (d held in regs) ==================
    float dk_[16] = {0,0,0,0,0,0,0,0,0,0,0,0,0,0,0,0};
    gemm3(sb, B_AKHI, B_AKLO, lane, m0, n0, dk_);
#pragma unroll
    for (int t = 0; t < 4; ++t) {
        int c = n0 + 8 * t + cb;
        float2 bb = __ldg(reinterpret_cast<const float2*>(bk + c));
        dk_[4*t] += bb.x; dk_[4*t+1] += bb.y; dk_[4*t+2] += bb.x; dk_[4*t+3] += bb.y;
    }
    __syncthreads();
    stageW(Wv);
    __syncthreads();

    // ================= V = xk @ Wv + bv =================
    {
        float d[16] = {0,0,0,0,0,0,0,0,0,0,0,0,0,0,0,0};
        gemm3(sb, B_AKHI, B_AKLO, lane, m0, n0, d);
        __syncthreads();   // AK (xk) and W (Wv) now dead
        // Kb -> AK region (natural [key][feat]); Vb -> VB region
#pragma unroll
        for (int t = 0; t < 4; ++t) {
            int c = n0 + 8 * t + cb;
            float2 bb = __ldg(reinterpret_cast<const float2*>(bv + c));
            stsplit(B_AKHI, B_AKLO, r1,     c, dk_[4*t],   dk_[4*t+1]);
            stsplit(B_AKHI, B_AKLO, r1 + 8, c, dk_[4*t+2], dk_[4*t+3]);
            stsplit(B_VBHI, B_VBLO, r1,     c, d[4*t]   + bb.x, d[4*t+1] + bb.y);
            stsplit(B_VBHI, B_VBLO, r1 + 8, c, d[4*t+2] + bb.x, d[4*t+3] + bb.y);
        }
        // XTb: target features natural [key][feat] bf16 hi/lo
        for (int u = tid; u < 2048; u += NT) {
            int m = u >> 5, k0 = 4 * (u & 31);
            u64 hi, lo;
            bsplit4(__ldg(reinterpret_cast<const float4*>(xt_src + m * D + k0)), hi, lo);
            *reinterpret_cast<u64*>(smc + B_XTHI + m * 272 + k0 * 2) = hi;
            *reinterpret_cast<u64*>(smc + B_XTLO + m * 272 + k0 * 2) = lo;
        }
    }
    __syncthreads();

    // ================= middle: S, TV, CT fully in mma/registers ===========
    {
        const int h = wid >> 1, mh = wid & 1;
        const int q4 = lane & 3, rl = lane >> 2;
        const u32 hoff = (u32)(h * 32);
        float tvs[2][8], cts[2][8];
#pragma unroll
        for (int s = 0; s < 2; ++s) {
            const int m0t = 32 * mh + 16 * s;
            // Q A-frag (k = head feats)
            u32 qh[4], ql[4];
            u32 aadr = (u32)((m0t + (lane & 15)) * 272) + hoff + (u32)((lane >> 4) * 16);
            ldsm4(qh, sb + B_AQHI + aadr);
            ldsm4(ql, sb + B_AQLO + aadr);
            // S per 16-key block; convert to A-frags immediately
            u32 sh_[4][4], sl_[4][4];
            const u32 badr = (u32)(((lane & 7) + ((lane >> 4) << 3)) * 272) + hoff
                           + (u32)(((lane >> 3) & 1) * 16);
            float* attn = out + ((size_t)bn * H + h) * (L * L);
#pragma unroll
            for (int nb = 0; nb < 4; ++nb) {
                u32 kh[4], kl[4];
                u32 ba = badr + (u32)(nb * 16 * 272);
                ldsm4(kh, sb + B_AKHI + ba);
                ldsm4(kl, sb + B_AKLO + ba);
                float db[8] = {0,0,0,0,0,0,0,0};
                mmabf(db,     qh, kh[0], kh[1]);  mmabf(db + 4, qh, kh[2], kh[3]);
                mmabf(db,     qh, kl[0], kl[1]);  mmabf(db + 4, qh, kl[2], kl[3]);
                mmabf(db,     ql, kh[0], kh[1]);  mmabf(db + 4, ql, kh[2], kh[3]);
#pragma unroll
                for (int i = 0; i < 8; i++) db[i] *= 0.25f;
                int r = m0t + rl, c = nb * 16 + 2 * q4;
                *reinterpret_cast<float2*>(attn + r * L + c)           = make_float2(db[0], db[1]);
                *reinterpret_cast<float2*>(attn + (r + 8) * L + c)     = make_float2(db[2], db[3]);
                *reinterpret_cast<float2*>(attn + r * L + c + 8)       = make_float2(db[4], db[5]);
                *reinterpret_cast<float2*>(attn + (r + 8) * L + c + 8) = make_float2(db[6], db[7]);
                split2(db[0], db[1], sh_[nb][0], sl_[nb][0]);
                split2(db[2], db[3], sh_[nb][1], sl_[nb][1]);
                split2(db[4], db[5], sh_[nb][2], sl_[nb][2]);
                split2(db[6], db[7], sh_[nb][3], sl_[nb][3]);
            }
            // TV = S @ V, CT = S @ XT  (B via ldmatrix.trans from [key][feat])
            float tvd[8] = {0,0,0,0,0,0,0,0}, ctd[8] = {0,0,0,0,0,0,0,0};
            const u32 tadr = (u32)(((lane & 7) + 8 * ((lane >> 3) & 1)) * 272) + hoff
                           + (u32)((lane >> 4) * 16);
#pragma unroll
            for (int kt = 0; kt < 4; ++kt) {
                u32 off = tadr + (u32)(kt * 16 * 272);
                u32 vh[4], vl[4], xh[4], xl[4];
                ldsm4t(vh, sb + B_VBHI + off);
                ldsm4t(vl, sb + B_VBLO + off);
                ldsm4t(xh, sb + B_XTHI + off);
                ldsm4t(xl, sb + B_XTLO + off);
                mmabf(tvd,     sh_[kt], vh[0], vh[1]);  mmabf(tvd + 4, sh_[kt], vh[2], vh[3]);
                mmabf(tvd,     sh_[kt], vl[0], vl[1]);  mmabf(tvd + 4, sh_[kt], vl[2], vl[3]);
                mmabf(tvd,     sl_[kt], vh[0], vh[1]);  mmabf(tvd + 4, sl_[kt], vh[2], vh[3]);
                mmabf(ctd,     sh_[kt], xh[0], xh[1]);  mmabf(ctd + 4, sh_[kt], xh[2], xh[3]);
                mmabf(ctd,     sh_[kt], xl[0], xl[1]);  mmabf(ctd + 4, sh_[kt], xl[2], xl[3]);
                mmabf(ctd,     sl_[kt], xh[0], xh[1]);  mmabf(ctd + 4, sl_[kt], xh[2], xh[3]);
            }
#pragma unroll
            for (int i = 0; i < 8; i++) { tvs[s][i] = tvd[i]; cts[s][i] = ctd[i]; }
        }
        __syncthreads();   // all Qa/Kb/Vb/XTb reads done
        // write TV -> AQ region, CT -> AK region (bf16 A-layout)
#pragma unroll
        for (int s = 0; s < 2; ++s) {
            int rr = 32 * mh + 16 * s + rl;
#pragma unroll
            for (int j = 0; j < 2; ++j) {
                int c = h * 16 + 8 * j + 2 * q4;
                stsplit(B_AQHI, B_AQLO, rr,     c, tvs[s][4*j],   tvs[s][4*j+1]);
                stsplit(B_AQHI, B_AQLO, rr + 8, c, tvs[s][4*j+2], tvs[s][4*j+3]);
                stsplit(B_AKHI, B_AKLO, rr,     c, cts[s][4*j],   cts[s][4*j+1]);
                stsplit(B_AKHI, B_AKLO, rr + 8, c, cts[s][4*j+2], cts[s][4*j+3]);
            }
        }
        stageW(Wot);   // W region (Vb/XTb) dead
    }
    __syncthreads();

    // ================= epilogue: 2 projections + LayerNorm =================
#pragma unroll 1
    for (int br = 0; br < 2; ++br) {
        const int aHi = br ? B_AKHI : B_AQHI;
        const int aLo = br ? B_AKLO : B_AQLO;
        const int fbase = br ? 8704 : 0;   // f32 proj buffer (stride 132) over same region

        float d[16] = {0,0,0,0,0,0,0,0,0,0,0,0,0,0,0,0};
        gemm3(sb, (u32)aHi, (u32)aLo, lane, m0, n0, d);
        __syncthreads();   // all bf16 A reads done before f32 overwrite
#pragma unroll
        for (int t = 0; t < 4; ++t) {
            int c = n0 + 8 * t + cb;
            *reinterpret_cast<float2*>(sm + fbase + r1 * 132 + c) =
                make_float2(d[4*t], d[4*t+1]);
            *reinterpret_cast<float2*>(sm + fbase + (r1 + 8) * 132 + c) =
                make_float2(d[4*t+2], d[4*t+3]);
        }
        if (br == 0) stageW(Wtg);
        __syncthreads();

        // LN: warp owns rows 4*wid..4*wid+3
        {
            const float* bias = br ? btg : bot;
            const float* gam  = br ? g_tgt : g_time;
            const float* bet  = br ? b_tgt : b_time;
            float* dstg = br ? ct_base : tv_base;
            const int c0 = 4 * lane;
            float4 bb = __ldg(reinterpret_cast<const float4*>(bias + c0));
            float4 gv = __ldg(reinterpret_cast<const float4*>(gam + c0));
            float4 be = __ldg(reinterpret_cast<const float4*>(bet + c0));
#pragma unroll
            for (int i = 0; i < 4; ++i) {
                int r = 4 * wid + i;
                float4 x = *reinterpret_cast<const float4*>(sm + fbase + r * 132 + c0);
                float v0 = x.x + bb.x, v1 = x.y + bb.y, v2 = x.z + bb.z, v3 = x.w + bb.w;
                if (br == 0) {
                    float4 xr = __ldg(reinterpret_cast<const float4*>(xq_src + r * D + c0));
                    v0 += xr.x; v1 += xr.y; v2 += xr.z; v3 += xr.w;
                }
                float s1 = v0 + v1 + v2 + v3;
                float s2 = v0*v0 + v1*v1 + v2*v2 + v3*v3;
#pragma unroll
                for (int o = 16; o; o >>= 1) {
                    s1 += __shfl_xor_sync(0xffffffffu, s1, o);
                    s2 += __shfl_xor_sync(0xffffffffu, s2, o);
                }
                float mean = s1 * (1.0f / 128.0f);
                float var  = s2 * (1.0f / 128.0f) - mean * mean;
                float rstd = rsqrtf(var + 1e-5f);
                float4 y;
                y.x = (v0 - mean) * rstd * gv.x + be.x;
                y.y = (v1 - mean) * rstd * gv.y + be.y;
                y.z = (v2 - mean) * rstd * gv.z + be.z;
                y.w = (v3 - mean) * rstd * gv.w + be.w;
                *reinterpret_cast<float4*>(dstg + r * D + c0) = y;
            }
        }
        __syncthreads();
    }
}

extern "C" void kernel_launch(void* const* d_in, const int* in_sizes, int n_in,
                              void* d_out, int out_size) {
    const float* xq  = (const float*)d_in[0];
    const float* xk  = (const float*)d_in[1];
    const float* xt  = (const float*)d_in[2];
    const float* Wq  = (const float*)d_in[3];
    const float* bq  = (const float*)d_in[4];
    const float* Wk  = (const float*)d_in[5];
    const float* bk  = (const float*)d_in[6];
    const float* Wv  = (const float*)d_in[7];
    const float* bv  = (const float*)d_in[8];
    const float* Wot = (const float*)d_in[9];
    const float* bot = (const float*)d_in[10];
    const float* Wtg = (const float*)d_in[11];
    const float* btg = (const float*)d_in[12];
    const float* g_time = (const float*)d_in[13];
    const float* b_time = (const float*)d_in[14];
    const float* g_tgt  = (const float*)d_in[15];
    const float* b_tgt  = (const float*)d_in[16];
    float* out = (float*)d_out;

    int BN = in_sizes[0] / (L * D);

    cudaFuncSetAttribute(fused_attn_kernel,
                         cudaFuncAttributeMaxDynamicSharedMemorySize, SM_BYTES);
    fused_attn_kernel<<<BN, NT, SM_BYTES>>>(
        xq, xk, xt, Wq, bq, Wk, bk, Wv, bv, Wot, bot, Wtg, btg,
        g_time, b_time, g_tgt, b_tgt, out, BN);
}

// round 17
// speedup vs baseline: 1.0212x; 1.0212x over previous
#include <cuda_runtime.h>
#include <cuda_bf16.h>

#define NT 512
typedef unsigned long long u64;
typedef unsigned int u32;
typedef unsigned short u16;

static constexpr int L = 64, D = 128, H = 8;

// ---- byte offsets (all bf16 regions stride 272B) ----
static constexpr int B_AQHI = 0;       // xq hi -> Qa hi ; epilogue f32 buf br0
static constexpr int B_AQLO = 17408;   // xq lo -> Qa lo
static constexpr int B_AKHI = 34816;   // xk hi -> Kb hi ; epilogue f32 buf br1
static constexpr int B_AKLO = 52224;   // xk lo -> Kb lo
static constexpr int B_WHI  = 69632;   // W hi | Vb hi/lo
static constexpr int B_WLO  = 104448;  // W lo | XTb hi/lo
static constexpr int B_VBHI = 69632;
static constexpr int B_VBLO = 87040;
static constexpr int B_XTHI = 104448;
static constexpr int B_XTLO = 121856;
static constexpr int B_TVHI = 139264;  // TV bf16 hi
static constexpr int B_TVLO = 156672;
static constexpr int B_CTHI = 174080;  // CT bf16 hi
static constexpr int B_CTLO = 191488;
static constexpr int SM_BYTES = 208896;

// ---------------- helpers ----------------
static __device__ __forceinline__ void ldsm4(u32* r, u32 addr) {
    asm volatile("ldmatrix.sync.aligned.m8n8.x4.shared.b16 {%0,%1,%2,%3}, [%4];"
        : "=r"(r[0]), "=r"(r[1]), "=r"(r[2]), "=r"(r[3]) : "r"(addr));
}
static __device__ __forceinline__ void ldsm4t(u32* r, u32 addr) {
    asm volatile("ldmatrix.sync.aligned.m8n8.x4.trans.shared.b16 {%0,%1,%2,%3}, [%4];"
        : "=r"(r[0]), "=r"(r[1]), "=r"(r[2]), "=r"(r[3]) : "r"(addr));
}
static __device__ __forceinline__ void mmabf(float* d, const u32* a, u32 b0, u32 b1) {
    asm volatile("mma.sync.aligned.m16n8k16.row.col.f32.bf16.bf16.f32 "
        "{%0,%1,%2,%3}, {%4,%5,%6,%7}, {%8,%9}, {%0,%1,%2,%3};"
        : "+f"(d[0]), "+f"(d[1]), "+f"(d[2]), "+f"(d[3])
        : "r"(a[0]), "r"(a[1]), "r"(a[2]), "r"(a[3]), "r"(b0), "r"(b1));
}
static __device__ __forceinline__ void split2(float a, float b, u32& hi, u32& lo) {
    __nv_bfloat162 h2 = __floats2bfloat162_rn(a, b);
    __nv_bfloat162 l2 = __floats2bfloat162_rn(a - __bfloat162float(h2.x),
                                              b - __bfloat162float(h2.y));
    hi = *reinterpret_cast<u32*>(&h2);
    lo = *reinterpret_cast<u32*>(&l2);
}
static __device__ __forceinline__ void bsplit4(float4 v, u64& hi, u64& lo) {
    u16 h[4], l[4];
    float x[4] = {v.x, v.y, v.z, v.w};
#pragma unroll
    for (int i = 0; i < 4; i++) {
        __nv_bfloat16 bh = __float2bfloat16(x[i]);
        h[i] = __bfloat16_as_ushort(bh);
        l[i] = __bfloat16_as_ushort(__float2bfloat16(x[i] - __bfloat162float(bh)));
    }
    hi = (u64)h[0] | ((u64)h[1] << 16) | ((u64)h[2] << 32) | ((u64)h[3] << 48);
    lo = (u64)l[0] | ((u64)l[1] << 16) | ((u64)l[2] << 32) | ((u64)l[3] << 48);
}

// 3-pass bf16-split GEMM 64x128x128: warp tile 16m x 32n. A/W stride 272B.
static __device__ __forceinline__ void gemm3(u32 sb, u32 aHi, u32 aLo,
                                             int lane, int m0, int n0, float d[16]) {
    const u32 aoff = (u32)((m0 + (lane & 15)) * 272 + (lane >> 4) * 16);
    const u32 brow = (u32)(((lane & 7) + ((lane >> 4) << 3)) * 272 + ((lane >> 3) & 1) * 16);
    const u32 b0o = brow + (u32)(n0 * 272);
    const u32 b1o = b0o + 16 * 272;
#pragma unroll
    for (int kk = 0; kk < 8; ++kk) {
        const u32 ka = (u32)(kk * 32);
        u32 ah[4], al[4], bh0[4], bh1[4], bl0[4], bl1[4];
        ldsm4(ah, sb + aHi + aoff + ka);
        ldsm4(al, sb + aLo + aoff + ka);
        ldsm4(bh0, sb + B_WHI + b0o + ka);
        ldsm4(bh1, sb + B_WHI + b1o + ka);
        ldsm4(bl0, sb + B_WLO + b0o + ka);
        ldsm4(bl1, sb + B_WLO + b1o + ka);
#pragma unroll
        for (int t = 0; t < 4; ++t) {
            const u32* bh = (t < 2) ? bh0 : bh1;
            const u32* bl = (t < 2) ? bl0 : bl1;
            const int s = (t & 1) * 2;
            mmabf(d + 4 * t, ah, bh[s], bh[s + 1]);
            mmabf(d + 4 * t, ah, bl[s], bl[s + 1]);
            mmabf(d + 4 * t, al, bh[s], bh[s + 1]);
        }
    }
}

__global__ void __launch_bounds__(NT, 1)
fused_attn_kernel(const float* __restrict__ xq_g, const float* __restrict__ xk_g,
                  const float* __restrict__ xt_g,
                  const float* __restrict__ Wq,  const float* __restrict__ bq,
                  const float* __restrict__ Wk,  const float* __restrict__ bk,
                  const float* __restrict__ Wv,  const float* __restrict__ bv,
                  const float* __restrict__ Wot, const float* __restrict__ bot,
                  const float* __restrict__ Wtg, const float* __restrict__ btg,
                  const float* __restrict__ g_time, const float* __restrict__ b_time,
                  const float* __restrict__ g_tgt,  const float* __restrict__ b_tgt,
                  float* __restrict__ out, int BN)
{
    extern __shared__ float sm[];
    char* smc = reinterpret_cast<char*>(sm);
    const u32 sb = (u32)__cvta_generic_to_shared(sm);
    const int tid = threadIdx.x, bn = blockIdx.x;
    const int wid = tid >> 5, lane = tid & 31;
    const int m0 = 16 * (wid >> 2), n0 = 32 * (wid & 3);
    const int r1 = m0 + (lane >> 2), cb = 2 * (lane & 3);

    const float* xq_src = xq_g + (size_t)bn * (L * D);
    const float* xk_src = xk_g + (size_t)bn * (L * D);
    const float* xt_src = xt_g + (size_t)bn * (L * D);

    const size_t attnElems = (size_t)BN * H * (L * L);
    float* tv_base = out + attnElems + (size_t)bn * (L * D);
    float* ct_base = out + attnElems + (size_t)BN * (L * D) + (size_t)bn * (L * D);

    // W^T bf16 hi/lo stager: B[n][k] = W[k][n], stride 272B
    auto stageW = [&](const float* W) {
        for (int u = tid; u < 4096; u += NT) {
            int n = u & 127, k0 = 4 * (u >> 7);
            float4 v;
            v.x = __ldg(W + (k0 + 0) * D + n);
            v.y = __ldg(W + (k0 + 1) * D + n);
            v.z = __ldg(W + (k0 + 2) * D + n);
            v.w = __ldg(W + (k0 + 3) * D + n);
            u64 hi, lo; bsplit4(v, hi, lo);
            *reinterpret_cast<u64*>(smc + B_WHI + n * 272 + k0 * 2) = hi;
            *reinterpret_cast<u64*>(smc + B_WLO + n * 272 + k0 * 2) = lo;
        }
    };
    auto stsplit = [&](int baseHi, int baseLo, int r, int c, float a, float b) {
        u32 hi, lo; split2(a, b, hi, lo);
        *reinterpret_cast<u32*>(smc + baseHi + r * 272 + c * 2) = hi;
        *reinterpret_cast<u32*>(smc + baseLo + r * 272 + c * 2) = lo;
    };

    // ---- stage xq, xk bf16 hi/lo ----
    for (int u = tid; u < 2048; u += NT) {
        int m = u >> 5, k0 = 4 * (u & 31);
        u64 hi, lo;
        bsplit4(__ldg(reinterpret_cast<const float4*>(xq_src + m * D + k0)), hi, lo);
        *reinterpret_cast<u64*>(smc + B_AQHI + m * 272 + k0 * 2) = hi;
        *reinterpret_cast<u64*>(smc + B_AQLO + m * 272 + k0 * 2) = lo;
        bsplit4(__ldg(reinterpret_cast<const float4*>(xk_src + m * D + k0)), hi, lo);
        *reinterpret_cast<u64*>(smc + B_AKHI + m * 272 + k0 * 2) = hi;
        *reinterpret_cast<u64*>(smc + B_AKLO + m * 272 + k0 * 2) = lo;
    }
    stageW(Wq);
    __syncthreads();

    // ================= Q = xq @ Wq + bq -> Qa (A-layout, over AQ) =========
    {
        float d[16] = {0,0,0,0,0,0,0,0,0,0,0,0,0,0,0,0};
        gemm3(sb, B_AQHI, B_AQLO, lane, m0, n0, d);
        __syncthreads();
#pragma unroll
        for (int t = 0; t < 4; ++t) {
            int c = n0 + 8 * t + cb;
            float2 bb = __ldg(reinterpret_cast<const float2*>(bq + c));
            stsplit(B_AQHI, B_AQLO, r1,     c, d[4*t]   + bb.x, d[4*t+1] + bb.y);
            stsplit(B_AQHI, B_AQLO, r1 + 8, c, d[4*t+2] + bb.x, d[4*t+3] + bb.y);
        }
        stageW(Wk);
    }
    __syncthreads();

    // ================= K = xk @ Wk + bk (d held in regs) ==================
    float dk_[16] = {0,0,0,0,0,0,0,0,0,0,0,0,0,0,0,0};
    gemm3(sb, B_AKHI, B_AKLO, lane, m0, n0, dk_);
#pragma unroll
    for (int t = 0; t < 4; ++t) {
        int c = n0 + 8 * t + cb;
        float2 bb = __ldg(reinterpret_cast<const float2*>(bk + c));
        dk_[4*t] += bb.x; dk_[4*t+1] += bb.y; dk_[4*t+2] += bb.x; dk_[4*t+3] += bb.y;
    }
    __syncthreads();
    stageW(Wv);
    __syncthreads();

    // ================= V = xk @ Wv + bv =================
    {
        float d[16] = {0,0,0,0,0,0,0,0,0,0,0,0,0,0,0,0};
        gemm3(sb, B_AKHI, B_AKLO, lane, m0, n0, d);
        __syncthreads();   // AK (xk) and W (Wv) now dead
        // Kb -> AK region (natural [key][feat]); Vb -> VB region
#pragma unroll
        for (int t = 0; t < 4; ++t) {
            int c = n0 + 8 * t + cb;
            float2 bb = __ldg(reinterpret_cast<const float2*>(bv + c));
            stsplit(B_AKHI, B_AKLO, r1,     c, dk_[4*t],   dk_[4*t+1]);
            stsplit(B_AKHI, B_AKLO, r1 + 8, c, dk_[4*t+2], dk_[4*t+3]);
            stsplit(B_VBHI, B_VBLO, r1,     c, d[4*t]   + bb.x, d[4*t+1] + bb.y);
            stsplit(B_VBHI, B_VBLO, r1 + 8, c, d[4*t+2] + bb.x, d[4*t+3] + bb.y);
        }
        // XTb: target features natural [key][feat] bf16 hi/lo
        for (int u = tid; u < 2048; u += NT) {
            int m = u >> 5, k0 = 4 * (u & 31);
            u64 hi, lo;
            bsplit4(__ldg(reinterpret_cast<const float4*>(xt_src + m * D + k0)), hi, lo);
            *reinterpret_cast<u64*>(smc + B_XTHI + m * 272 + k0 * 2) = hi;
            *reinterpret_cast<u64*>(smc + B_XTLO + m * 272 + k0 * 2) = lo;
        }
    }
    __syncthreads();

    // ================= middle: S, TV, CT in mma; fused per key-block ======
    // warp = (head h, m-half mh); no intra-middle syncs (writes go to fresh
    // TV/CT regions + global attn only).
    {
        const int h = wid >> 1, mh = wid & 1;
        const int q4 = lane & 3, rl = lane >> 2;
        const u32 hoff = (u32)(h * 32);
        float* attn = out + ((size_t)bn * H + h) * (L * L);
        const u32 badr = (u32)(((lane & 7) + ((lane >> 4) << 3)) * 272) + hoff
                       + (u32)(((lane >> 3) & 1) * 16);
        const u32 tadr = (u32)(((lane & 7) + 8 * ((lane >> 3) & 1)) * 272) + hoff
                       + (u32)((lane >> 4) * 16);
#pragma unroll 1
        for (int s = 0; s < 2; ++s) {
            const int m0t = 32 * mh + 16 * s;
            u32 qh[4], ql[4];
            u32 aadr = (u32)((m0t + (lane & 15)) * 272) + hoff + (u32)((lane >> 4) * 16);
            ldsm4(qh, sb + B_AQHI + aadr);
            ldsm4(ql, sb + B_AQLO + aadr);
            float tvd[8] = {0,0,0,0,0,0,0,0}, ctd[8] = {0,0,0,0,0,0,0,0};
#pragma unroll
            for (int nb = 0; nb < 4; ++nb) {
                // S block (16 keys)
                u32 kh[4], kl[4];
                u32 ba = badr + (u32)(nb * 16 * 272);
                ldsm4(kh, sb + B_AKHI + ba);
                ldsm4(kl, sb + B_AKLO + ba);
                float db[8] = {0,0,0,0,0,0,0,0};
                mmabf(db,     qh, kh[0], kh[1]);  mmabf(db + 4, qh, kh[2], kh[3]);
                mmabf(db,     qh, kl[0], kl[1]);  mmabf(db + 4, qh, kl[2], kl[3]);
                mmabf(db,     ql, kh[0], kh[1]);  mmabf(db + 4, ql, kh[2], kh[3]);
#pragma unroll
                for (int i = 0; i < 8; i++) db[i] *= 0.25f;
                int r = m0t + rl, c = nb * 16 + 2 * q4;
                *reinterpret_cast<float2*>(attn + r * L + c)           = make_float2(db[0], db[1]);
                *reinterpret_cast<float2*>(attn + (r + 8) * L + c)     = make_float2(db[2], db[3]);
                *reinterpret_cast<float2*>(attn + r * L + c + 8)       = make_float2(db[4], db[5]);
                *reinterpret_cast<float2*>(attn + (r + 8) * L + c + 8) = make_float2(db[6], db[7]);
                // S -> A-frags (transient)
                u32 sh_[4], sl_[4];
                split2(db[0], db[1], sh_[0], sl_[0]);
                split2(db[2], db[3], sh_[1], sl_[1]);
                split2(db[4], db[5], sh_[2], sl_[2]);
                split2(db[6], db[7], sh_[3], sl_[3]);
                // apply this key block to TV and CT
                u32 off = tadr + (u32)(nb * 16 * 272);
                u32 vh[4], vl[4], xh[4], xl[4];
                ldsm4t(vh, sb + B_VBHI + off);
                ldsm4t(vl, sb + B_VBLO + off);
                ldsm4t(xh, sb + B_XTHI + off);
                ldsm4t(xl, sb + B_XTLO + off);
                mmabf(tvd,     sh_, vh[0], vh[1]);  mmabf(tvd + 4, sh_, vh[2], vh[3]);
                mmabf(tvd,     sh_, vl[0], vl[1]);  mmabf(tvd + 4, sh_, vl[2], vl[3]);
                mmabf(tvd,     sl_, vh[0], vh[1]);  mmabf(tvd + 4, sl_, vh[2], vh[3]);
                mmabf(ctd,     sh_, xh[0], xh[1]);  mmabf(ctd + 4, sh_, xh[2], xh[3]);
                mmabf(ctd,     sh_, xl[0], xl[1]);  mmabf(ctd + 4, sh_, xl[2], xl[3]);
                mmabf(ctd,     sl_, xh[0], xh[1]);  mmabf(ctd + 4, sl_, xh[2], xh[3]);
            }
            // immediate write to dedicated TV/CT regions (bf16 A-layout)
            int rr = m0t + rl;
#pragma unroll
            for (int j = 0; j < 2; ++j) {
                int c = h * 16 + 8 * j + 2 * q4;
                stsplit(B_TVHI, B_TVLO, rr,     c, tvd[4*j],   tvd[4*j+1]);
                stsplit(B_TVHI, B_TVLO, rr + 8, c, tvd[4*j+2], tvd[4*j+3]);
                stsplit(B_CTHI, B_CTLO, rr,     c, ctd[4*j],   ctd[4*j+1]);
                stsplit(B_CTHI, B_CTLO, rr + 8, c, ctd[4*j+2], ctd[4*j+3]);
            }
        }
    }
    __syncthreads();       // ALL Vb/XTb reads done before W restage (race fix)
    stageW(Wot);
    __syncthreads();

    // ================= epilogue: 2 projections + LayerNorm =================
#pragma unroll 1
    for (int br = 0; br < 2; ++br) {
        const u32 aHi = br ? B_CTHI : B_TVHI;
        const u32 aLo = br ? B_CTLO : B_TVLO;
        const int fbase = br ? 8704 : 0;   // f32 proj buffer (stride 132) over AQ/AK

        float d[16] = {0,0,0,0,0,0,0,0,0,0,0,0,0,0,0,0};
        gemm3(sb, aHi, aLo, lane, m0, n0, d);
        __syncthreads();   // all W reads done before restage
#pragma unroll
        for (int t = 0; t < 4; ++t) {
            int c = n0 + 8 * t + cb;
            *reinterpret_cast<float2*>(sm + fbase + r1 * 132 + c) =
                make_float2(d[4*t], d[4*t+1]);
            *reinterpret_cast<float2*>(sm + fbase + (r1 + 8) * 132 + c) =
                make_float2(d[4*t+2], d[4*t+3]);
        }
        if (br == 0) stageW(Wtg);
        __syncthreads();

        // LN: warp owns rows 4*wid..4*wid+3
        {
            const float* bias = br ? btg : bot;
            const float* gam  = br ? g_tgt : g_time;
            const float* bet  = br ? b_tgt : b_time;
            float* dstg = br ? ct_base : tv_base;
            const int c0 = 4 * lane;
            float4 bb = __ldg(reinterpret_cast<const float4*>(bias + c0));
            float4 gv = __ldg(reinterpret_cast<const float4*>(gam + c0));
            float4 be = __ldg(reinterpret_cast<const float4*>(bet + c0));
#pragma unroll
            for (int i = 0; i < 4; ++i) {
                int r = 4 * wid + i;
                float4 x = *reinterpret_cast<const float4*>(sm + fbase + r * 132 + c0);
                float v0 = x.x + bb.x, v1 = x.y + bb.y, v2 = x.z + bb.z, v3 = x.w + bb.w;
                if (br == 0) {
                    float4 xr = __ldg(reinterpret_cast<const float4*>(xq_src + r * D + c0));
                    v0 += xr.x; v1 += xr.y; v2 += xr.z; v3 += xr.w;
                }
                float s1 = v0 + v1 + v2 + v3;
                float s2 = v0*v0 + v1*v1 + v2*v2 + v3*v3;
#pragma unroll
                for (int o = 16; o; o >>= 1) {
                    s1 += __shfl_xor_sync(0xffffffffu, s1, o);
                    s2 += __shfl_xor_sync(0xffffffffu, s2, o);
                }
                float mean = s1 * (1.0f / 128.0f);
                float var  = s2 * (1.0f / 128.0f) - mean * mean;
                float rstd = rsqrtf(var + 1e-5f);
                float4 y;
                y.x = (v0 - mean) * rstd * gv.x + be.x;
                y.y = (v1 - mean) * rstd * gv.y + be.y;
                y.z = (v2 - mean) * rstd * gv.z + be.z;
                y.w = (v3 - mean) * rstd * gv.w + be.w;
                *reinterpret_cast<float4*>(dstg + r * D + c0) = y;
            }
        }
        __syncthreads();
    }
}

extern "C" void kernel_launch(void* const* d_in, const int* in_sizes, int n_in,
                              void* d_out, int out_size) {
    const float* xq  = (const float*)d_in[0];
    const float* xk  = (const float*)d_in[1];
    const float* xt  = (const float*)d_in[2];
    const float* Wq  = (const float*)d_in[3];
    const float* bq  = (const float*)d_in[4];
    const float* Wk  = (const float*)d_in[5];
    const float* bk  = (const float*)d_in[6];
    const float* Wv  = (const float*)d_in[7];
    const float* bv  = (const float*)d_in[8];
    const float* Wot = (const float*)d_in[9];
    const float* bot = (const float*)d_in[10];
    const float* Wtg = (const float*)d_in[11];
    const float* btg = (const float*)d_in[12];
    const float* g_time = (const float*)d_in[13];
    const float* b_time = (const float*)d_in[14];
    const float* g_tgt  = (const float*)d_in[15];
    const float* b_tgt  = (const float*)d_in[16];
    float* out = (float*)d_out;

    int BN = in_sizes[0] / (L * D);

    cudaFuncSetAttribute(fused_attn_kernel,
                         cudaFuncAttributeMaxDynamicSharedMemorySize, SM_BYTES);
    fused_attn_kernel<<<BN, NT, SM_BYTES>>>(
        xq, xk, xt, Wq, bq, Wk, bk, Wv, bv, Wot, bot, Wtg, btg,
        g_time, b_time, g_tgt, b_tgt, out, BN);
}